// round 2
// baseline (speedup 1.0000x reference)
#include <cuda_runtime.h>
#include <stdint.h>

// Problem shape (from reference): D = 64 floats per row -> 16 float4 per row.
#define D4 16           // float4 per row
#define MAX_NODES 262144

__device__ float g_counts[MAX_NODES];
__device__ int   g_is64;   // 1 if edge_index is int64, 0 if int32

__device__ __forceinline__ void red_add_v4(float* addr, float4 v) {
    asm volatile("red.global.add.v4.f32 [%0], {%1, %2, %3, %4};"
                 :: "l"(addr), "f"(v.x), "f"(v.y), "f"(v.z), "f"(v.w)
                 : "memory");
}

// Detect edge_index dtype. For int64 data with values in [0, n_nodes), every
// odd 32-bit word is a (zero) high word. For int32 data, odd words are random
// node ids; the chance 64 of them are all zero is ~0.
__global__ void na_detect_kernel(const int* __restrict__ ei_words) {
    int acc = ei_words[1 + 2 * threadIdx.x];   // odd words 1,3,...,127
    // warp-reduce OR
    #pragma unroll
    for (int off = 16; off > 0; off >>= 1)
        acc |= __shfl_xor_sync(0xffffffffu, acc, off);
    if (threadIdx.x == 0) g_is64 = (acc == 0) ? 1 : 0;
}

// Init: self-loop contribution (out = Z) and counts = 1.
__global__ void na_init_kernel(const float4* __restrict__ Zr,
                               const float4* __restrict__ Zi,
                               float4* __restrict__ outr,
                               float4* __restrict__ outi,
                               int total4, int n_nodes) {
    int i = blockIdx.x * blockDim.x + threadIdx.x;
    if (i < total4) {
        outr[i] = Zr[i];
        outi[i] = Zi[i];
    }
    if (i < n_nodes) {
        g_counts[i] = 1.0f;
    }
}

// One warp per edge. Lanes 0-15: real row float4s, lanes 16-31: imag row float4s.
__global__ void na_edge_kernel(const float4* __restrict__ Zr,
                               const float4* __restrict__ Zi,
                               const void* __restrict__ ei_raw,
                               float4* __restrict__ outr,
                               float4* __restrict__ outi,
                               int n_edges) {
    int warp = (blockIdx.x * blockDim.x + threadIdx.x) >> 5;
    if (warp >= n_edges) return;
    int lane = threadIdx.x & 31;

    // warp-uniform index loads (all lanes same address -> L1 broadcast)
    int src, dst;
    if (g_is64) {
        const long long* ei = (const long long*)ei_raw;
        src = (int)__ldg(ei + warp);
        dst = (int)__ldg(ei + n_edges + warp);
    } else {
        const int* ei = (const int*)ei_raw;
        src = __ldg(ei + warp);
        dst = __ldg(ei + n_edges + warp);
    }

    int c = lane & 15;
    const float4* srcp;
    float4* dstp;
    if (lane < 16) { srcp = Zr; dstp = outr; }
    else           { srcp = Zi; dstp = outi; }

    float4 v = __ldg(srcp + (size_t)src * D4 + c);
    red_add_v4((float*)(dstp + (size_t)dst * D4 + c), v);

    if (lane == 0) {
        atomicAdd(&g_counts[dst], 1.0f);
    }
}

// Normalize by in-degree (count >= 1 always, self-loop included).
__global__ void na_norm_kernel(float4* __restrict__ outr,
                               float4* __restrict__ outi,
                               int total4) {
    int i = blockIdx.x * blockDim.x + threadIdx.x;
    if (i >= total4) return;
    float inv = 1.0f / g_counts[i >> 4];   // i / D4, D4 == 16
    float4 r = outr[i];
    float4 m = outi[i];
    r.x *= inv; r.y *= inv; r.z *= inv; r.w *= inv;
    m.x *= inv; m.y *= inv; m.z *= inv; m.w *= inv;
    outr[i] = r;
    outi[i] = m;
}

extern "C" void kernel_launch(void* const* d_in, const int* in_sizes, int n_in,
                              void* d_out, int out_size) {
    const float4* Zr = (const float4*)d_in[0];
    const float4* Zi = (const float4*)d_in[1];
    const void*   ei = d_in[2];

    int n_nodes = in_sizes[0] / 64;          // D = 64
    int n_edges = in_sizes[2] / 2;           // edge_index is (2, E), elem count
    int total4  = n_nodes * D4;              // float4 elements per output array

    float* out = (float*)d_out;
    float4* outr = (float4*)out;                               // first half: A_real
    float4* outi = (float4*)(out + (size_t)n_nodes * 64);      // second half: A_imag

    const int T = 256;

    // 0) dtype detection (1 warp; reads first 128 int32 words, safe either way)
    na_detect_kernel<<<1, 64>>>((const int*)ei);

    // 1) init (self-loop + counts)
    na_init_kernel<<<(total4 + T - 1) / T, T>>>(Zr, Zi, outr, outi, total4, n_nodes);

    // 2) edge scatter-add: one warp per edge -> n_edges*32 threads
    long long threads_needed = (long long)n_edges * 32;
    int blocks = (int)((threads_needed + T - 1) / T);
    na_edge_kernel<<<blocks, T>>>(Zr, Zi, ei, outr, outi, n_edges);

    // 3) normalize
    na_norm_kernel<<<(total4 + T - 1) / T, T>>>(outr, outi, total4);
}